// round 6
// baseline (speedup 1.0000x reference)
#include <cuda_runtime.h>

#define NB 16384
#define NK 64
#define ND 128

// ---------------- scratch (device globals: no allocation allowed) ----------------
__device__ int   g_cnt[NK];
__device__ int   g_off[NK];
__device__ int   g_cursor[NK];
__device__ int   g_assign[NB];
__device__ int   g_bucket[NB];
__device__ float g_sum[NK * ND];
__device__ float g_mean[NK * ND];

typedef unsigned long long u64;

__device__ __forceinline__ u64 pk2(float a, float b) {
    u64 r; asm("mov.b64 %0,{%1,%2};" : "=l"(r) : "f"(a), "f"(b)); return r;
}
__device__ __forceinline__ void fma2(u64& d, u64 a, u64 b) {
    asm("fma.rn.f32x2 %0,%1,%2,%0;" : "+l"(d) : "l"(a), "l"(b));
}
__device__ __forceinline__ float2 up2(u64 v) {
    float2 r; asm("mov.b64 {%0,%1},%2;" : "=f"(r.x), "=f"(r.y) : "l"(v)); return r;
}

// ---------------- kernel 0: zero scratch ----------------
__global__ void k_init() {
    int i = blockIdx.x * blockDim.x + threadIdx.x;
    if (i < NK * ND) g_sum[i] = 0.f;
    if (i < NK) { g_cnt[i] = 0; g_cursor[i] = 0; }
}

// ---------------- kernel 1: distances, log-softmax, argmin, cluster sums ----------------
// grid = 256 blocks * 256 threads, 64 rows per block.
// smem: cT [128][66] transposed centers, xs [64][132] row tile, cn2 [64]
#define SMEM1_FLOATS (ND * 66 + 64 * 132 + NK)

__global__ void __launch_bounds__(256, 2) k_pass1(const float* __restrict__ x,
                                                  const float* __restrict__ centers,
                                                  float* __restrict__ out)
{
    extern __shared__ float sm[];
    float* cT  = sm;                       // 128*66
    float* xs  = sm + ND * 66;             // 64*132
    float* cn2 = sm + ND * 66 + 64 * 132;  // 64

    const int tid  = threadIdx.x;
    const int lane = tid & 31;
    const int wrp  = tid >> 5;     // 0..7
    const int rowbase = blockIdx.x * 64;

    // stage centers transposed (coalesced global read)
    for (int idx = tid; idx < NK * ND; idx += 256) {
        int k = idx >> 7, d = idx & 127;
        cT[d * 66 + k] = centers[idx];
    }
    // stage x tile, row-major with pad (conflict-free float4 stores)
    #pragma unroll
    for (int j = 0; j < 8; ++j) {
        int idx = tid + 256 * j;          // float4 units, 0..2047
        int r = idx >> 5, c4 = idx & 31;
        float4 v = reinterpret_cast<const float4*>(x)[(rowbase + r) * 32 + c4];
        *reinterpret_cast<float4*>(&xs[r * 132 + c4 * 4]) = v;
    }
    __syncthreads();

    if (tid < NK) {
        float s = 0.f;
        for (int d = 0; d < ND; ++d) { float c = cT[d * 66 + tid]; s += c * c; }
        cn2[tid] = s;
    }
    __syncthreads();

    // main: dot(x_row, c_k) for 8 rows (this warp) x 2 clusters (this lane)
    float acc[8][2];
    #pragma unroll
    for (int i = 0; i < 8; ++i) { acc[i][0] = 0.f; acc[i][1] = 0.f; }
    const int r0 = wrp * 8;

    #pragma unroll 2
    for (int d4 = 0; d4 < 32; ++d4) {
        float4 xv[8];
        #pragma unroll
        for (int i = 0; i < 8; ++i)
            xv[i] = *reinterpret_cast<const float4*>(&xs[(r0 + i) * 132 + d4 * 4]);
        float2 c0 = *reinterpret_cast<const float2*>(&cT[(d4 * 4 + 0) * 66 + lane * 2]);
        float2 c1 = *reinterpret_cast<const float2*>(&cT[(d4 * 4 + 1) * 66 + lane * 2]);
        float2 c2 = *reinterpret_cast<const float2*>(&cT[(d4 * 4 + 2) * 66 + lane * 2]);
        float2 c3 = *reinterpret_cast<const float2*>(&cT[(d4 * 4 + 3) * 66 + lane * 2]);
        #pragma unroll
        for (int i = 0; i < 8; ++i) {
            acc[i][0] += xv[i].x * c0.x + xv[i].y * c1.x + xv[i].z * c2.x + xv[i].w * c3.x;
            acc[i][1] += xv[i].x * c0.y + xv[i].y * c1.y + xv[i].z * c2.y + xv[i].w * c3.y;
        }
    }

    const float2 cc = *reinterpret_cast<const float2*>(&cn2[lane * 2]);
    const float LCLIP = -18.4206807f;   // logf(1e-8f)

    #pragma unroll 1
    for (int i = 0; i < 8; ++i) {
        const int r = r0 + i;
        const int row = rowbase + r;
        // ||x||^2
        float x0 = xs[r * 132 + lane];
        float x1 = xs[r * 132 + lane + 32];
        float x2 = xs[r * 132 + lane + 64];
        float x3 = xs[r * 132 + lane + 96];
        float p = x0 * x0 + x1 * x1 + x2 * x2 + x3 * x3;
        #pragma unroll
        for (int o = 16; o; o >>= 1) p += __shfl_xor_sync(0xffffffffu, p, o);

        float d0 = p - 2.f * acc[i][0] + cc.x;
        float d1 = p - 2.f * acc[i][1] + cc.y;

        // argmin (first-occurrence tiebreak, matching jnp.argmin)
        float mv; int mi;
        if (d0 <= d1) { mv = d0; mi = lane * 2; } else { mv = d1; mi = lane * 2 + 1; }
        #pragma unroll
        for (int o = 16; o; o >>= 1) {
            float ov = __shfl_xor_sync(0xffffffffu, mv, o);
            int   oi = __shfl_xor_sync(0xffffffffu, mi, o);
            if (ov < mv || (ov == mv && oi < mi)) { mv = ov; mi = oi; }
        }

        // log-softmax of expo = -0.5*dist
        float me = -0.5f * mv;
        float s0 = -0.5f * d0 - me;
        float s1 = -0.5f * d1 - me;
        float e = expf(s0) + expf(s1);
        #pragma unroll
        for (int o = 16; o; o >>= 1) e += __shfl_xor_sync(0xffffffffu, e, o);
        float lse = logf(e);
        float l0 = fmaxf(s0 - lse, LCLIP);
        float l1 = fmaxf(s1 - lse, LCLIP);
        *reinterpret_cast<float2*>(&out[row * NK + lane * 2]) = make_float2(l0, l1);

        // cluster statistics (fire-and-forget global reductions)
        if (lane == 0) { g_assign[row] = mi; atomicAdd(&g_cnt[mi], 1); }
        float* dst = g_sum + mi * ND;
        atomicAdd(dst + lane,      x0);
        atomicAdd(dst + lane + 32, x1);
        atomicAdd(dst + lane + 64, x2);
        atomicAdd(dst + lane + 96, x3);
    }
}

// ---------------- kernel 2: means, offsets, mean_mse; zero covar slot ----------------
__global__ void k_stats(const float* __restrict__ centers, float* __restrict__ out)
{
    __shared__ float red[256];
    const int tid = threadIdx.x;

    for (int idx = tid; idx < NK * ND; idx += 256) {
        float w = (float)g_cnt[idx >> 7];
        g_mean[idx] = g_sum[idx] / (w + 1e-7f);
    }
    __syncthreads();

    if (tid == 0) {
        int o = 0;
        for (int k = 0; k < NK; ++k) { g_off[k] = o; o += g_cnt[k]; }
    }

    float local = 0.f;
    if (tid < NK) {
        float s = 0.f;
        const float* m = g_mean + tid * ND;
        const float* c = centers + tid * ND;
        for (int d = 0; d < ND; ++d) { float df = m[d] - c[d]; s += df * df; }
        local = (float)g_cnt[tid] * s;
    }
    red[tid] = local;
    __syncthreads();
    for (int st = 128; st; st >>= 1) {
        if (tid < st) red[tid] += red[tid + st];
        __syncthreads();
    }
    if (tid == 0) {
        out[(size_t)NB * NK]     = red[0] / (float)(NB * ND);
        out[(size_t)NB * NK + 1] = 0.f;   // covar kernel accumulates here
    }
}

// ---------------- kernel 3: bucket rows by cluster ----------------
__global__ void k_scatter() {
    int n = blockIdx.x * blockDim.x + threadIdx.x;
    int a = g_assign[n];
    int p = atomicAdd(&g_cursor[a], 1);
    g_bucket[g_off[a] + p] = n;
}

// ---------------- kernel 4: per-cluster SYRK -> covar_mse ----------------
// grid = 128 blocks = 64 clusters x 2 column slices of S (128 x 64 each).
// per thread: 4 (di) x 8 (dj) accumulator tile via packed fma.rn.f32x2.
__global__ void __launch_bounds__(256) k_covar(const float* __restrict__ x,
                                               float* __restrict__ out)
{
    __shared__ float m[ND];
    __shared__ float xs[32 * 132];
    __shared__ float red[8];

    const int tid = threadIdx.x;
    const int ty = tid & 31;      // lane: di block
    const int tx = tid >> 5;      // warp: dj block
    const int k = blockIdx.x >> 1;
    const int slice = blockIdx.x & 1;
    const int dj0 = slice * 64 + tx * 8;

    if (tid < ND) m[tid] = g_mean[k * ND + tid];
    const int cnt = g_cnt[k];
    const int start = g_off[k];

    u64 acc[4][4];
    #pragma unroll
    for (int i = 0; i < 4; ++i)
        #pragma unroll
        for (int j = 0; j < 4; ++j) acc[i][j] = 0ULL;
    __syncthreads();

    for (int base = 0; base < cnt; base += 32) {
        __syncthreads();
        // stage 32 centered rows (zeros for tail)
        #pragma unroll
        for (int t = 0; t < 4; ++t) {
            int idx = tid + 256 * t;       // float4 units, 0..1023
            int r = idx >> 5, c4 = idx & 31;
            float4 v;
            if (base + r < cnt) {
                int row = g_bucket[start + base + r];
                float4 xv = reinterpret_cast<const float4*>(x)[row * 32 + c4];
                float4 mv = *reinterpret_cast<const float4*>(&m[c4 * 4]);
                v = make_float4(xv.x - mv.x, xv.y - mv.y, xv.z - mv.z, xv.w - mv.w);
            } else {
                v = make_float4(0.f, 0.f, 0.f, 0.f);
            }
            *reinterpret_cast<float4*>(&xs[r * 132 + c4 * 4]) = v;
        }
        __syncthreads();

        #pragma unroll 2
        for (int r = 0; r < 32; ++r) {
            float4 a4 = *reinterpret_cast<const float4*>(&xs[r * 132 + ty * 4]);
            const ulonglong2* bp = reinterpret_cast<const ulonglong2*>(&xs[r * 132 + dj0]);
            ulonglong2 q0 = bp[0];
            ulonglong2 q1 = bp[1];
            u64 aa0 = pk2(a4.x, a4.x), aa1 = pk2(a4.y, a4.y);
            u64 aa2 = pk2(a4.z, a4.z), aa3 = pk2(a4.w, a4.w);
            u64 b0 = q0.x, b1 = q0.y, b2 = q1.x, b3 = q1.y;
            fma2(acc[0][0], aa0, b0); fma2(acc[0][1], aa0, b1); fma2(acc[0][2], aa0, b2); fma2(acc[0][3], aa0, b3);
            fma2(acc[1][0], aa1, b0); fma2(acc[1][1], aa1, b1); fma2(acc[1][2], aa1, b2); fma2(acc[1][3], aa1, b3);
            fma2(acc[2][0], aa2, b0); fma2(acc[2][1], aa2, b1); fma2(acc[2][2], aa2, b2); fma2(acc[2][3], aa2, b3);
            fma2(acc[3][0], aa3, b0); fma2(acc[3][1], aa3, b1); fma2(acc[3][2], aa3, b2); fma2(acc[3][3], aa3, b3);
        }
    }

    // nonlinearity + weighted contribution
    const float w = (float)cnt;
    const float invw = 1.f / (w + 1e-7f);
    float diag = 0.f, offd = 0.f;
    #pragma unroll
    for (int i = 0; i < 4; ++i) {
        int di = ty * 4 + i;
        #pragma unroll
        for (int j = 0; j < 4; ++j) {
            float2 cv = up2(acc[i][j]);
            int dj = dj0 + 2 * j;
            float c0 = cv.x * invw;
            float c1 = cv.y * invw;
            if (di == dj)     { float t = c0 - 1.f; diag += t * t; } else offd += c0 * c0;
            if (di == dj + 1) { float t = c1 - 1.f; diag += t * t; } else offd += c1 * c1;
        }
    }
    float contrib = w * diag / (float)(NB * ND) + w * offd / 266338304.0f; // NB*ND*(ND-1)
    #pragma unroll
    for (int o = 16; o; o >>= 1) contrib += __shfl_xor_sync(0xffffffffu, contrib, o);
    if (ty == 0) red[tx] = contrib;
    __syncthreads();
    if (tid == 0) {
        float s = 0.f;
        #pragma unroll
        for (int i = 0; i < 8; ++i) s += red[i];
        atomicAdd(&out[(size_t)NB * NK + 1], s);
    }
}

// ---------------- launch ----------------
extern "C" void kernel_launch(void* const* d_in, const int* in_sizes, int n_in,
                              void* d_out, int out_size)
{
    const float* x = (const float*)d_in[0];
    const float* c = (const float*)d_in[1];
    float* out = (float*)d_out;

    const int smem1 = SMEM1_FLOATS * (int)sizeof(float);   // 67,840 B
    cudaFuncSetAttribute(k_pass1, cudaFuncAttributeMaxDynamicSharedMemorySize, smem1);

    k_init<<<32, 256>>>();
    k_pass1<<<NB / 64, 256, smem1>>>(x, c, out);
    k_stats<<<1, 256>>>(c, out);
    k_scatter<<<NB / 256, 256>>>();
    k_covar<<<NK * 2, 256>>>(x, out);
}

// round 7
// speedup vs baseline: 2.1075x; 2.1075x over previous
#include <cuda_runtime.h>

#define NB 16384
#define NK 64
#define ND 128
#define CHUNK 128                 // rows per covar work-group
#define MAXG 192                  // max groups: sum(ceil(cnt/128)) <= 191

// ---------------- scratch (device globals: no allocation allowed) ----------------
__device__ int   g_cnt[NK];
__device__ int   g_off[NK];
__device__ int   g_cursor[NK];
__device__ int   g_assign[NB];
__device__ int   g_bucket[NB];
__device__ float g_sum[NK * ND];
__device__ float g_mean[NK * ND];
// covar work-group tables + partial S buffers
__device__ int   g_grp_k[MAXG];       // group -> cluster
__device__ int   g_grp_start[MAXG];   // group -> row offset within cluster bucket
__device__ int   g_grp_base[NK];      // cluster -> first group id
__device__ int   g_ngrp[NK];          // cluster -> #groups
__device__ int   g_Gtotal;
__device__ float g_part[MAXG * 2 * 8192];   // 12.6 MB partial 128x64 S-slices

typedef unsigned long long u64;

__device__ __forceinline__ u64 pk2(float a, float b) {
    u64 r; asm("mov.b64 %0,{%1,%2};" : "=l"(r) : "f"(a), "f"(b)); return r;
}
__device__ __forceinline__ void fma2(u64& d, u64 a, u64 b) {
    asm("fma.rn.f32x2 %0,%1,%2,%0;" : "+l"(d) : "l"(a), "l"(b));
}
__device__ __forceinline__ float2 up2(u64 v) {
    float2 r; asm("mov.b64 {%0,%1},%2;" : "=f"(r.x), "=f"(r.y) : "l"(v)); return r;
}

// ---------------- kernel 0: zero scratch ----------------
__global__ void k_init() {
    int i = blockIdx.x * blockDim.x + threadIdx.x;
    if (i < NK * ND) g_sum[i] = 0.f;
    if (i < NK) { g_cnt[i] = 0; g_cursor[i] = 0; }
}

// ---------------- kernel 1: distances, log-softmax, argmin, cluster sums ----------------
// grid = 256 blocks * 256 threads, 64 rows per block. (unchanged from passing version)
#define SMEM1_FLOATS (ND * 66 + 64 * 132 + NK)

__global__ void __launch_bounds__(256, 2) k_pass1(const float* __restrict__ x,
                                                  const float* __restrict__ centers,
                                                  float* __restrict__ out)
{
    extern __shared__ float sm[];
    float* cT  = sm;                       // 128*66
    float* xs  = sm + ND * 66;             // 64*132
    float* cn2 = sm + ND * 66 + 64 * 132;  // 64

    const int tid  = threadIdx.x;
    const int lane = tid & 31;
    const int wrp  = tid >> 5;     // 0..7
    const int rowbase = blockIdx.x * 64;

    for (int idx = tid; idx < NK * ND; idx += 256) {
        int k = idx >> 7, d = idx & 127;
        cT[d * 66 + k] = centers[idx];
    }
    #pragma unroll
    for (int j = 0; j < 8; ++j) {
        int idx = tid + 256 * j;
        int r = idx >> 5, c4 = idx & 31;
        float4 v = reinterpret_cast<const float4*>(x)[(rowbase + r) * 32 + c4];
        *reinterpret_cast<float4*>(&xs[r * 132 + c4 * 4]) = v;
    }
    __syncthreads();

    if (tid < NK) {
        float s = 0.f;
        for (int d = 0; d < ND; ++d) { float c = cT[d * 66 + tid]; s += c * c; }
        cn2[tid] = s;
    }
    __syncthreads();

    float acc[8][2];
    #pragma unroll
    for (int i = 0; i < 8; ++i) { acc[i][0] = 0.f; acc[i][1] = 0.f; }
    const int r0 = wrp * 8;

    #pragma unroll 2
    for (int d4 = 0; d4 < 32; ++d4) {
        float4 xv[8];
        #pragma unroll
        for (int i = 0; i < 8; ++i)
            xv[i] = *reinterpret_cast<const float4*>(&xs[(r0 + i) * 132 + d4 * 4]);
        float2 c0 = *reinterpret_cast<const float2*>(&cT[(d4 * 4 + 0) * 66 + lane * 2]);
        float2 c1 = *reinterpret_cast<const float2*>(&cT[(d4 * 4 + 1) * 66 + lane * 2]);
        float2 c2 = *reinterpret_cast<const float2*>(&cT[(d4 * 4 + 2) * 66 + lane * 2]);
        float2 c3 = *reinterpret_cast<const float2*>(&cT[(d4 * 4 + 3) * 66 + lane * 2]);
        #pragma unroll
        for (int i = 0; i < 8; ++i) {
            acc[i][0] += xv[i].x * c0.x + xv[i].y * c1.x + xv[i].z * c2.x + xv[i].w * c3.x;
            acc[i][1] += xv[i].x * c0.y + xv[i].y * c1.y + xv[i].z * c2.y + xv[i].w * c3.y;
        }
    }

    const float2 cc = *reinterpret_cast<const float2*>(&cn2[lane * 2]);
    const float LCLIP = -18.4206807f;   // logf(1e-8f)

    #pragma unroll 1
    for (int i = 0; i < 8; ++i) {
        const int r = r0 + i;
        const int row = rowbase + r;
        float x0 = xs[r * 132 + lane];
        float x1 = xs[r * 132 + lane + 32];
        float x2 = xs[r * 132 + lane + 64];
        float x3 = xs[r * 132 + lane + 96];
        float p = x0 * x0 + x1 * x1 + x2 * x2 + x3 * x3;
        #pragma unroll
        for (int o = 16; o; o >>= 1) p += __shfl_xor_sync(0xffffffffu, p, o);

        float d0 = p - 2.f * acc[i][0] + cc.x;
        float d1 = p - 2.f * acc[i][1] + cc.y;

        float mv; int mi;
        if (d0 <= d1) { mv = d0; mi = lane * 2; } else { mv = d1; mi = lane * 2 + 1; }
        #pragma unroll
        for (int o = 16; o; o >>= 1) {
            float ov = __shfl_xor_sync(0xffffffffu, mv, o);
            int   oi = __shfl_xor_sync(0xffffffffu, mi, o);
            if (ov < mv || (ov == mv && oi < mi)) { mv = ov; mi = oi; }
        }

        float me = -0.5f * mv;
        float s0 = -0.5f * d0 - me;
        float s1 = -0.5f * d1 - me;
        float e = expf(s0) + expf(s1);
        #pragma unroll
        for (int o = 16; o; o >>= 1) e += __shfl_xor_sync(0xffffffffu, e, o);
        float lse = logf(e);
        float l0 = fmaxf(s0 - lse, LCLIP);
        float l1 = fmaxf(s1 - lse, LCLIP);
        *reinterpret_cast<float2*>(&out[row * NK + lane * 2]) = make_float2(l0, l1);

        if (lane == 0) { g_assign[row] = mi; atomicAdd(&g_cnt[mi], 1); }
        float* dst = g_sum + mi * ND;
        atomicAdd(dst + lane,      x0);
        atomicAdd(dst + lane + 32, x1);
        atomicAdd(dst + lane + 64, x2);
        atomicAdd(dst + lane + 96, x3);
    }
}

// ---------------- kernel 2: means, offsets, group tables, mean_mse ----------------
__global__ void k_stats(const float* __restrict__ centers, float* __restrict__ out)
{
    __shared__ float red[256];
    const int tid = threadIdx.x;

    for (int idx = tid; idx < NK * ND; idx += 256) {
        float w = (float)g_cnt[idx >> 7];
        g_mean[idx] = g_sum[idx] / (w + 1e-7f);
    }
    __syncthreads();

    if (tid == 0) {
        int o = 0, go = 0;
        for (int k = 0; k < NK; ++k) {
            int c = g_cnt[k];
            g_off[k] = o; o += c;
            g_grp_base[k] = go;
            int ng = (c + CHUNK - 1) / CHUNK;
            g_ngrp[k] = ng;
            for (int j = 0; j < ng; ++j) {
                g_grp_k[go + j] = k;
                g_grp_start[go + j] = j * CHUNK;
            }
            go += ng;
        }
        g_Gtotal = go;
    }

    float local = 0.f;
    if (tid < NK) {
        float s = 0.f;
        const float* m = g_mean + tid * ND;
        const float* c = centers + tid * ND;
        for (int d = 0; d < ND; ++d) { float df = m[d] - c[d]; s += df * df; }
        local = (float)g_cnt[tid] * s;
    }
    red[tid] = local;
    __syncthreads();
    for (int st = 128; st; st >>= 1) {
        if (tid < st) red[tid] += red[tid + st];
        __syncthreads();
    }
    if (tid == 0) {
        out[(size_t)NB * NK]     = red[0] / (float)(NB * ND);
        out[(size_t)NB * NK + 1] = 0.f;   // k_final accumulates here
    }
}

// ---------------- kernel 3: bucket rows by cluster (block-aggregated atomics) ----------------
__global__ void __launch_bounds__(1024) k_scatter() {
    __shared__ int hcnt[NK];
    __shared__ int hbase[NK];
    const int tid = threadIdx.x;
    if (tid < NK) hcnt[tid] = 0;
    __syncthreads();
    const int n = blockIdx.x * 1024 + tid;
    const int a = g_assign[n];
    const int lp = atomicAdd(&hcnt[a], 1);
    __syncthreads();
    if (tid < NK) hbase[tid] = atomicAdd(&g_cursor[tid], hcnt[tid]);
    __syncthreads();
    g_bucket[g_off[a] + hbase[a] + lp] = n;
}

// ---------------- kernel 4: balanced per-group SYRK partials ----------------
// grid = 2*MAXG blocks; block (g, slice) handles <=128 rows of cluster g_grp_k[g],
// producing a 128x64 partial S-slice via packed fma.rn.f32x2.
__global__ void __launch_bounds__(256) k_covar(const float* __restrict__ x)
{
    __shared__ float m[ND];
    __shared__ float xs[32 * 132];

    const int tid = threadIdx.x;
    const int ty = tid & 31;      // lane: di block (4 rows of S)
    const int tx = tid >> 5;      // warp: dj block (8 cols of S)
    const int g = blockIdx.x >> 1;
    const int slice = blockIdx.x & 1;
    if (g >= g_Gtotal) return;
    const int k = g_grp_k[g];
    const int gstart = g_grp_start[g];
    const int cnt = g_cnt[k];
    const int nrows = min(CHUNK, cnt - gstart);
    const int rowstart = g_off[k] + gstart;
    const int dj0 = slice * 64 + tx * 8;

    if (tid < ND) m[tid] = g_mean[k * ND + tid];

    u64 acc[4][4];
    #pragma unroll
    for (int i = 0; i < 4; ++i)
        #pragma unroll
        for (int j = 0; j < 4; ++j) acc[i][j] = 0ULL;
    __syncthreads();

    for (int base = 0; base < nrows; base += 32) {
        __syncthreads();
        #pragma unroll
        for (int t = 0; t < 4; ++t) {
            int idx = tid + 256 * t;       // float4 units, 0..1023
            int r = idx >> 5, c4 = idx & 31;
            float4 v;
            if (base + r < nrows) {
                int row = g_bucket[rowstart + base + r];
                float4 xv = reinterpret_cast<const float4*>(x)[row * 32 + c4];
                float4 mv = *reinterpret_cast<const float4*>(&m[c4 * 4]);
                v = make_float4(xv.x - mv.x, xv.y - mv.y, xv.z - mv.z, xv.w - mv.w);
            } else {
                v = make_float4(0.f, 0.f, 0.f, 0.f);
            }
            *reinterpret_cast<float4*>(&xs[r * 132 + c4 * 4]) = v;
        }
        __syncthreads();

        #pragma unroll 2
        for (int r = 0; r < 32; ++r) {
            float4 a4 = *reinterpret_cast<const float4*>(&xs[r * 132 + ty * 4]);
            const ulonglong2* bp = reinterpret_cast<const ulonglong2*>(&xs[r * 132 + dj0]);
            ulonglong2 q0 = bp[0];
            ulonglong2 q1 = bp[1];
            u64 aa0 = pk2(a4.x, a4.x), aa1 = pk2(a4.y, a4.y);
            u64 aa2 = pk2(a4.z, a4.z), aa3 = pk2(a4.w, a4.w);
            u64 b0 = q0.x, b1 = q0.y, b2 = q1.x, b3 = q1.y;
            fma2(acc[0][0], aa0, b0); fma2(acc[0][1], aa0, b1); fma2(acc[0][2], aa0, b2); fma2(acc[0][3], aa0, b3);
            fma2(acc[1][0], aa1, b0); fma2(acc[1][1], aa1, b1); fma2(acc[1][2], aa1, b2); fma2(acc[1][3], aa1, b3);
            fma2(acc[2][0], aa2, b0); fma2(acc[2][1], aa2, b1); fma2(acc[2][2], aa2, b2); fma2(acc[2][3], aa2, b3);
            fma2(acc[3][0], aa3, b0); fma2(acc[3][1], aa3, b1); fma2(acc[3][2], aa3, b2); fma2(acc[3][3], aa3, b3);
        }
    }

    // write partial S-slice: entry idx = di*64 + dj_local
    float* p = g_part + (size_t)(g * 2 + slice) * 8192;
    #pragma unroll
    for (int i = 0; i < 4; ++i) {
        const int di = ty * 4 + i;
        #pragma unroll
        for (int j = 0; j < 4; ++j) {
            float2 cv = up2(acc[i][j]);
            *reinterpret_cast<float2*>(&p[di * 64 + tx * 8 + 2 * j]) = cv;
        }
    }
}

// ---------------- kernel 5: reduce partials + nonlinearity -> covar_mse ----------------
__global__ void __launch_bounds__(256) k_final(float* __restrict__ out)
{
    __shared__ float red[8];
    const int tid = threadIdx.x;
    const int k = blockIdx.x >> 1;
    const int slice = blockIdx.x & 1;
    const int ngrp = g_ngrp[k];
    const int base = g_grp_base[k];
    const float w = (float)g_cnt[k];
    const float invw = 1.f / (w + 1e-7f);
    const float wd = w / (float)(NB * ND);
    const float wo = w / 266338304.0f;   // NB*ND*(ND-1)

    float acc[32];
    #pragma unroll
    for (int i = 0; i < 32; ++i) acc[i] = 0.f;
    for (int j = 0; j < ngrp; ++j) {
        const float* p = g_part + (size_t)((base + j) * 2 + slice) * 8192;
        #pragma unroll
        for (int i = 0; i < 32; ++i) acc[i] += p[tid + 256 * i];
    }

    float s = 0.f;
    #pragma unroll
    for (int i = 0; i < 32; ++i) {
        int idx = tid + 256 * i;
        int di = idx >> 6;
        int dj = slice * 64 + (idx & 63);
        float c = acc[i] * invw;
        if (di == dj) { float t = c - 1.f; s += t * t * wd; }
        else          s += c * c * wo;
    }
    #pragma unroll
    for (int o = 16; o; o >>= 1) s += __shfl_xor_sync(0xffffffffu, s, o);
    if ((tid & 31) == 0) red[tid >> 5] = s;
    __syncthreads();
    if (tid == 0) {
        float t = 0.f;
        #pragma unroll
        for (int i = 0; i < 8; ++i) t += red[i];
        atomicAdd(&out[(size_t)NB * NK + 1], t);
    }
}

// ---------------- launch ----------------
extern "C" void kernel_launch(void* const* d_in, const int* in_sizes, int n_in,
                              void* d_out, int out_size)
{
    const float* x = (const float*)d_in[0];
    const float* c = (const float*)d_in[1];
    float* out = (float*)d_out;

    const int smem1 = SMEM1_FLOATS * (int)sizeof(float);   // 67,840 B
    cudaFuncSetAttribute(k_pass1, cudaFuncAttributeMaxDynamicSharedMemorySize, smem1);

    k_init<<<32, 256>>>();
    k_pass1<<<NB / 64, 256, smem1>>>(x, c, out);
    k_stats<<<1, 256>>>(c, out);
    k_scatter<<<NB / 1024, 1024>>>();
    k_covar<<<2 * MAXG, 256>>>(x);
    k_final<<<2 * NK, 256>>>(out);
}

// round 11
// speedup vs baseline: 3.6930x; 1.7523x over previous
#include <cuda_runtime.h>

#define NB 16384
#define NK 64
#define ND 128
#define CHUNK 64
#define MAXG 320     // sum(ceil(cnt/64)) <= 256 + 63 = 319

// ---------------- scratch (device globals: no allocation allowed) ----------------
__device__ int   g_cnt[NK];
__device__ int   g_off[NK];
__device__ int   g_cursor[NK];
__device__ int   g_assign[NB];
__device__ int   g_bucket[NB];
__device__ int   g_grp_k[MAXG];       // group -> cluster
__device__ int   g_grp_start[MAXG];   // group -> row offset within cluster bucket
__device__ int   g_grp_base[NK];      // cluster -> first group id
__device__ int   g_ngrp[NK];          // cluster -> #groups
__device__ int   g_Gtotal;
__device__ __align__(16) float g_gsum[MAXG * ND];        // per-group x-sums
__device__ __align__(16) float g_part[MAXG * 2 * 8192];  // per-(group,slice) 128x64 S partials (21 MB)

typedef unsigned long long u64;

__device__ __forceinline__ u64 pk2(float a, float b) {
    u64 r; asm("mov.b64 %0,{%1,%2};" : "=l"(r) : "f"(a), "f"(b)); return r;
}
__device__ __forceinline__ void fma2(u64& d, u64 a, u64 b) {
    asm("fma.rn.f32x2 %0,%1,%2,%0;" : "+l"(d) : "l"(a), "l"(b));
}
__device__ __forceinline__ float2 up2(u64 v) {
    float2 r; asm("mov.b64 {%0,%1},%2;" : "=f"(r.x), "=f"(r.y) : "l"(v)); return r;
}

// ---------------- kernel 0: zero the tiny counters ----------------
__global__ void k_init() {
    int i = threadIdx.x;
    if (i < NK) { g_cnt[i] = 0; g_cursor[i] = 0; }
}

// ---------------- kernel 1: distances, log-softmax, argmin, counts ----------------
// grid = 256 blocks * 256 threads, 64 rows per block.
// smem: cs2 [64][132] centers, row (k&1)*32+(k>>1)  (16B-aligned rows, conflict-free
//       LDS.128 in 8-lane phases);  xs [64][132];  cn2 [64]
#define SMEM1_FLOATS (64 * 132 + 64 * 132 + NK)

__global__ void __launch_bounds__(256, 2) k_pass1(const float* __restrict__ x,
                                                  const float* __restrict__ centers,
                                                  float* __restrict__ out)
{
    extern __shared__ __align__(16) float sm[];
    float* cs2 = sm;                        // 64 x 132, permuted rows
    float* xs  = sm + 64 * 132;             // 64 x 132
    float* cn2 = sm + 2 * 64 * 132;         // 64

    const int tid  = threadIdx.x;
    const int lane = tid & 31;
    const int wrp  = tid >> 5;     // 0..7
    const int rowbase = blockIdx.x * 64;

    // stage centers: cluster k -> row (k&1)*32 + (k>>1)
    for (int idx = tid; idx < NK * ND; idx += 256) {
        int k = idx >> 7, d = idx & 127;
        int r = ((k & 1) << 5) + (k >> 1);
        cs2[r * 132 + d] = centers[idx];
    }
    // stage x tile, row-major with pad
    #pragma unroll
    for (int j = 0; j < 8; ++j) {
        int idx = tid + 256 * j;          // float4 units, 0..2047
        int r = idx >> 5, c4 = idx & 31;
        float4 v = reinterpret_cast<const float4*>(x)[(rowbase + r) * 32 + c4];
        *reinterpret_cast<float4*>(&xs[r * 132 + c4 * 4]) = v;
    }
    __syncthreads();

    if (tid < NK) {
        int r = ((tid & 1) << 5) + (tid >> 1);
        float s = 0.f;
        #pragma unroll 4
        for (int d = 0; d < ND; ++d) { float c = cs2[r * 132 + d]; s += c * c; }
        cn2[tid] = s;
    }
    __syncthreads();

    // dot(x_row, c_k): 8 rows (this warp) x 2 clusters (this lane).
    // f32x2 pairing over even/odd dims -> zero packing movs.
    u64 acc[8][2];
    #pragma unroll
    for (int i = 0; i < 8; ++i) { acc[i][0] = 0ULL; acc[i][1] = 0ULL; }
    const int r0 = wrp * 8;
    const float* cA = &cs2[lane * 132];          // cluster 2*lane
    const float* cB = &cs2[(lane + 32) * 132];   // cluster 2*lane+1

    #pragma unroll 2
    for (int d4 = 0; d4 < 32; ++d4) {
        ulonglong2 ca = *reinterpret_cast<const ulonglong2*>(&cA[d4 * 4]);
        ulonglong2 cb = *reinterpret_cast<const ulonglong2*>(&cB[d4 * 4]);
        #pragma unroll
        for (int i = 0; i < 8; ++i) {
            ulonglong2 xv = *reinterpret_cast<const ulonglong2*>(&xs[(r0 + i) * 132 + d4 * 4]);
            fma2(acc[i][0], xv.x, ca.x);
            fma2(acc[i][1], xv.x, cb.x);
            fma2(acc[i][0], xv.y, ca.y);
            fma2(acc[i][1], xv.y, cb.y);
        }
    }

    const float2 cc = *reinterpret_cast<const float2*>(&cn2[lane * 2]);
    const float LCLIP = -18.4206807f;   // logf(1e-8f)

    #pragma unroll 1
    for (int i = 0; i < 8; ++i) {
        const int r = r0 + i;
        const int row = rowbase + r;
        float x0 = xs[r * 132 + lane];
        float x1 = xs[r * 132 + lane + 32];
        float x2 = xs[r * 132 + lane + 64];
        float x3 = xs[r * 132 + lane + 96];
        float p = x0 * x0 + x1 * x1 + x2 * x2 + x3 * x3;
        #pragma unroll
        for (int o = 16; o; o >>= 1) p += __shfl_xor_sync(0xffffffffu, p, o);

        float2 a0 = up2(acc[i][0]);
        float2 a1 = up2(acc[i][1]);
        float d0 = p - 2.f * (a0.x + a0.y) + cc.x;
        float d1 = p - 2.f * (a1.x + a1.y) + cc.y;

        // argmin (first-occurrence tiebreak, matching jnp.argmin)
        float mv; int mi;
        if (d0 <= d1) { mv = d0; mi = lane * 2; } else { mv = d1; mi = lane * 2 + 1; }
        #pragma unroll
        for (int o = 16; o; o >>= 1) {
            float ov = __shfl_xor_sync(0xffffffffu, mv, o);
            int   oi = __shfl_xor_sync(0xffffffffu, mi, o);
            if (ov < mv || (ov == mv && oi < mi)) { mv = ov; mi = oi; }
        }

        // log-softmax of expo = -0.5*dist
        float me = -0.5f * mv;
        float s0 = -0.5f * d0 - me;
        float s1 = -0.5f * d1 - me;
        float e = expf(s0) + expf(s1);
        #pragma unroll
        for (int o = 16; o; o >>= 1) e += __shfl_xor_sync(0xffffffffu, e, o);
        float lse = logf(e);
        float l0 = fmaxf(s0 - lse, LCLIP);
        float l1 = fmaxf(s1 - lse, LCLIP);
        *reinterpret_cast<float2*>(&out[row * NK + lane * 2]) = make_float2(l0, l1);

        if (lane == 0) { g_assign[row] = mi; atomicAdd(&g_cnt[mi], 1); }
    }
}

// ---------------- kernel 2: offsets + group tables (parallelized), zero scalars ----------------
__global__ void k_prep(float* __restrict__ out)
{
    __shared__ int scnt[NK];
    __shared__ int sgk[MAXG], sgs[MAXG];
    __shared__ int sgt;
    const int tid = threadIdx.x;
    if (tid < NK) scnt[tid] = g_cnt[tid];
    __syncthreads();
    if (tid == 0) {
        int o = 0, go = 0;
        for (int k = 0; k < NK; ++k) {
            int c = scnt[k];
            g_off[k] = o; o += c;
            g_grp_base[k] = go;
            int ng = (c + CHUNK - 1) / CHUNK;
            g_ngrp[k] = ng;
            for (int j = 0; j < ng; ++j) { sgk[go + j] = k; sgs[go + j] = j * CHUNK; }
            go += ng;
        }
        g_Gtotal = go; sgt = go;
        out[(size_t)NB * NK]     = 0.f;
        out[(size_t)NB * NK + 1] = 0.f;
    }
    __syncthreads();
    const int gt = sgt;
    for (int j = tid; j < gt; j += blockDim.x) { g_grp_k[j] = sgk[j]; g_grp_start[j] = sgs[j]; }
}

// ---------------- kernel 3: bucket rows by cluster (block-aggregated atomics) ----------------
__global__ void __launch_bounds__(256) k_scatter() {
    __shared__ int hcnt[NK];
    __shared__ int hbase[NK];
    const int tid = threadIdx.x;
    if (tid < NK) hcnt[tid] = 0;
    __syncthreads();
    const int n = blockIdx.x * 256 + tid;
    const int a = g_assign[n];
    const int lp = atomicAdd(&hcnt[a], 1);
    __syncthreads();
    if (tid < NK) hbase[tid] = atomicAdd(&g_cursor[tid], hcnt[tid]);
    __syncthreads();
    g_bucket[g_off[a] + hbase[a] + lp] = n;
}

// ---------------- kernel 4: persistent uncentered SYRK partials + group sums ----------------
// work items = (group, slice); static round-robin over grid=296 persistent blocks.
// item: <=64 rows, output 128x64 S-slice; per thread 4(di)x8(dj) via fma.rn.f32x2.
__global__ void __launch_bounds__(256, 2) k_covar(const float* __restrict__ x)
{
    __shared__ __align__(16) float xs[32 * 132];
    __shared__ __align__(16) float sp[8 * 132];

    const int tid = threadIdx.x;
    const int ty = tid & 31;      // lane: di block (4 rows of S)
    const int tx = tid >> 5;      // warp: dj block (8 cols of S)
    const int c4 = tid & 31;      // staging: fixed 4-dim group
    const int rslot = tid >> 5;   // staging: row slot
    const int nit = 2 * g_Gtotal;

    for (int it = blockIdx.x; it < nit; it += gridDim.x) {
        const int g = it >> 1;
        const int slice = it & 1;
        const int k = g_grp_k[g];
        const int gstart = g_grp_start[g];
        const int nrows = min(CHUNK, g_cnt[k] - gstart);
        const int rowstart = g_off[k] + gstart;
        const int dj0 = slice * 64 + tx * 8;

        u64 acc[4][4];
        #pragma unroll
        for (int i = 0; i < 4; ++i)
            #pragma unroll
            for (int j = 0; j < 4; ++j) acc[i][j] = 0ULL;
        float4 sum4 = make_float4(0.f, 0.f, 0.f, 0.f);

        for (int base = 0; base < nrows; base += 32) {
            __syncthreads();
            #pragma unroll
            for (int t = 0; t < 4; ++t) {
                int r = rslot + 8 * t;
                float4 v = make_float4(0.f, 0.f, 0.f, 0.f);
                if (base + r < nrows) {
                    int row = g_bucket[rowstart + base + r];
                    v = reinterpret_cast<const float4*>(x)[row * 32 + c4];
                }
                *reinterpret_cast<float4*>(&xs[r * 132 + c4 * 4]) = v;
                sum4.x += v.x; sum4.y += v.y; sum4.z += v.z; sum4.w += v.w;
            }
            __syncthreads();

            #pragma unroll 2
            for (int r = 0; r < 32; ++r) {
                float4 a4 = *reinterpret_cast<const float4*>(&xs[r * 132 + ty * 4]);
                const ulonglong2* bp = reinterpret_cast<const ulonglong2*>(&xs[r * 132 + dj0]);
                ulonglong2 q0 = bp[0];
                ulonglong2 q1 = bp[1];
                u64 aa0 = pk2(a4.x, a4.x), aa1 = pk2(a4.y, a4.y);
                u64 aa2 = pk2(a4.z, a4.z), aa3 = pk2(a4.w, a4.w);
                u64 b0 = q0.x, b1 = q0.y, b2 = q1.x, b3 = q1.y;
                fma2(acc[0][0], aa0, b0); fma2(acc[0][1], aa0, b1); fma2(acc[0][2], aa0, b2); fma2(acc[0][3], aa0, b3);
                fma2(acc[1][0], aa1, b0); fma2(acc[1][1], aa1, b1); fma2(acc[1][2], aa1, b2); fma2(acc[1][3], aa1, b3);
                fma2(acc[2][0], aa2, b0); fma2(acc[2][1], aa2, b1); fma2(acc[2][2], aa2, b2); fma2(acc[2][3], aa2, b3);
                fma2(acc[3][0], aa3, b0); fma2(acc[3][1], aa3, b1); fma2(acc[3][2], aa3, b2); fma2(acc[3][3], aa3, b3);
            }
        }

        // per-group x-sum (slice 0 writes it)
        __syncthreads();
        *reinterpret_cast<float4*>(&sp[rslot * 132 + c4 * 4]) = sum4;
        __syncthreads();
        if (slice == 0 && tid < ND) {
            float s = 0.f;
            #pragma unroll
            for (int q = 0; q < 8; ++q) s += sp[q * 132 + tid];
            g_gsum[g * ND + tid] = s;
        }

        // write uncentered partial S-slice
        float* p = g_part + (size_t)(g * 2 + slice) * 8192;
        #pragma unroll
        for (int i = 0; i < 4; ++i) {
            const int di = ty * 4 + i;
            #pragma unroll
            for (int j = 0; j < 4; ++j) {
                float2 cv = up2(acc[i][j]);
                *reinterpret_cast<float2*>(&p[di * 64 + tx * 8 + 2 * j]) = cv;
            }
        }
    }
}

// ---------------- kernel 5: assemble means + both MSEs ----------------
// grid = 64 clusters x 16 parts; block (k,part) reduces 8 di-rows x 128 dj.
__global__ void __launch_bounds__(256) k_final(const float* __restrict__ centers,
                                               float* __restrict__ out)
{
    __shared__ float sv[ND], mu[ND];
    __shared__ float red[8];
    const int tid = threadIdx.x;
    const int k = blockIdx.x >> 4;
    const int part = blockIdx.x & 15;
    const int ngrp = g_ngrp[k];
    const int base = g_grp_base[k];
    const float w = (float)g_cnt[k];
    const float invw = 1.f / (w + 1e-7f);

    if (tid < ND) {
        float s = 0.f;
        for (int j = 0; j < ngrp; ++j) s += g_gsum[(base + j) * ND + tid];
        sv[tid] = s; mu[tid] = s * invw;
    }
    __syncthreads();

    const int di  = part * 8 + (tid >> 5);
    const int dj0 = (tid & 31) * 4;
    const int slice = dj0 >> 6;
    const int djl = dj0 & 63;

    float4 S = make_float4(0.f, 0.f, 0.f, 0.f);
    for (int j = 0; j < ngrp; ++j) {
        float4 v = *reinterpret_cast<const float4*>(
            &g_part[(size_t)((base + j) * 2 + slice) * 8192 + di * 64 + djl]);
        S.x += v.x; S.y += v.y; S.z += v.z; S.w += v.w;
    }

    const float wd = w / (float)(NB * ND);
    const float wo = w / 266338304.0f;   // NB*ND*(ND-1)
    const float sdi = sv[di], mdi = mu[di];
    float Sc[4] = {S.x, S.y, S.z, S.w};
    float acc = 0.f;
    #pragma unroll
    for (int c = 0; c < 4; ++c) {
        int dj = dj0 + c;
        float tot = Sc[c] - sdi * mu[dj] - mdi * sv[dj] + w * mdi * mu[dj];
        float v = tot * invw;
        if (di == dj) { float t = v - 1.f; acc += t * t * wd; }
        else          acc += v * v * wo;
    }
    #pragma unroll
    for (int o = 16; o; o >>= 1) acc += __shfl_xor_sync(0xffffffffu, acc, o);
    if ((tid & 31) == 0) red[tid >> 5] = acc;
    __syncthreads();
    if (tid == 0) {
        float s = 0.f;
        #pragma unroll
        for (int i = 0; i < 8; ++i) s += red[i];
        atomicAdd(&out[(size_t)NB * NK + 1], s);
    }

    if (part == 0) {
        __syncthreads();
        float mloc = 0.f;
        if (tid < ND) { float df = mu[tid] - centers[k * ND + tid]; mloc = df * df; }
        #pragma unroll
        for (int o = 16; o; o >>= 1) mloc += __shfl_xor_sync(0xffffffffu, mloc, o);
        if ((tid & 31) == 0) red[tid >> 5] = mloc;
        __syncthreads();
        if (tid == 0) {
            float s = 0.f;
            #pragma unroll
            for (int i = 0; i < 8; ++i) s += red[i];
            atomicAdd(&out[(size_t)NB * NK], w * s / (float)(NB * ND));
        }
    }
}

// ---------------- launch ----------------
extern "C" void kernel_launch(void* const* d_in, const int* in_sizes, int n_in,
                              void* d_out, int out_size)
{
    const float* x = (const float*)d_in[0];
    const float* c = (const float*)d_in[1];
    float* out = (float*)d_out;

    const int smem1 = SMEM1_FLOATS * (int)sizeof(float);   // 67,840 B
    cudaFuncSetAttribute(k_pass1, cudaFuncAttributeMaxDynamicSharedMemorySize, smem1);

    k_init<<<1, 128>>>();
    k_pass1<<<NB / 64, 256, smem1>>>(x, c, out);
    k_prep<<<1, 256>>>(out);
    k_scatter<<<NB / 256, 256>>>();
    k_covar<<<296, 256>>>(x);
    k_final<<<NK * 16, 256>>>(c, out);
}